// round 3
// baseline (speedup 1.0000x reference)
#include <cuda_runtime.h>

// ---------------- configuration ----------------
#define TN   128          // nodes per tile
#define SP   132          // activation row stride (floats): %4==0 for LDS.128
#define KCH  8            // k rows per staged chunk (ping-pong)

// ---------------- shared memory layout (float offsets) ----------------
#define A256_OFF  0
#define A128_OFF  (256*SP)                   // 33792
#define STG0_OFF  (A128_OFF + 128*SP)        // 50688  (KCH*128 u64 = 2048 fl)
#define STG1_OFF  (STG0_OFF + KCH*128*2)     // 52736
#define C_B1      (STG1_OFF + KCH*128*2)     // 54784
#define C_BE1     (C_B1   + 256)
#define C_WE2     (C_BE1  + 128)             // 768 (128x6)
#define C_BE2     (C_WE2  + 768)             // 8 (6 used)
#define C_WD1D    (C_BE2  + 8)               // 1536: 6x128 duplicated u64
#define C_BD1     (C_WD1D + 1536)
#define C_BD2     (C_BD1  + 128)
#define C_BO      (C_BD2  + 256)
#define SMEM_FLOATS (C_BO + 4)
#define SMEM_BYTES  (SMEM_FLOATS * 4)        // 231,472 B <= 232,448 opt-in

typedef unsigned long long u64t;

__device__ __forceinline__ void fma2(u64t& d, u64t a, u64t b) {
    asm("fma.rn.f32x2 %0, %1, %2, %0;" : "+l"(d) : "l"(a), "l"(b));
}
__device__ __forceinline__ void unpack2(u64t v, float& lo, float& hi) {
    asm("mov.b64 {%0, %1}, %2;" : "=f"(lo), "=f"(hi) : "l"(v));
}
// tanh(x) = 1 - 2/(e^{2x}+1): clamp-free, 2 MUFU + 3 ALU, rel err ~1e-6
__device__ __forceinline__ float tanh_f(float x) {
    float e; asm("ex2.approx.f32 %0, %1;" : "=f"(e) : "f"(x * 2.885390082f));
    float r; asm("rcp.approx.f32 %0, %1;" : "=f"(r) : "f"(e + 1.0f));
    return fmaf(-2.0f, r, 1.0f);
}
__device__ __forceinline__ void lds128(u64t& a0, u64t& a1, const float* p) {
    const ulonglong2 v = *reinterpret_cast<const ulonglong2*>(p);
    a0 = v.x; a1 = v.y;
}

// ---------------- streamed GEMM over 128 output cols ----------------
// out[c][r] = (tanh?)( sum_k in[k][r] * W[k*ldw + coff + c] + bias[coff+c] )
// 512 threads: tx=tid&15 (cols c0+16j), ty=tid>>4 (rows r0=4ty, 2 f32x2 pairs).
// W staged into smem PRE-DUPLICATED as (w,w) u64 -> B operand is one LDS.64.
// Ping-pong staging, one barrier per stage, LDG prefetch overlapped with FMA.
template<int K, bool DOTANH>
__device__ __forceinline__ void gemm_stream(float* sm, int in_off,
        const float* __restrict__ W, int ldw, int coff, int bias_off, int out_off)
{
    const int tid = threadIdx.x;
    const int tx = tid & 15, ty = tid >> 4;
    const int r0 = ty * 4;
    const int srow = tid >> 6;           // staging: row within chunk (0..7)
    const int sc2  = (tid & 63) * 2;     // staging: col pair (0..126)

    u64t acc[2][8];
#pragma unroll
    for (int j = 0; j < 8; ++j) { acc[0][j] = 0ull; acc[1][j] = 0ull; }

    const int NST = K / KCH;
    // prologue: stage chunk 0 (duplicated)
    {
        float2 w = *reinterpret_cast<const float2*>(&W[(size_t)srow * ldw + coff + sc2]);
        float* p = &sm[STG0_OFF + (srow * 128 + sc2) * 2];
        *reinterpret_cast<float2*>(p)     = make_float2(w.x, w.x);
        *reinterpret_cast<float2*>(p + 2) = make_float2(w.y, w.y);
    }
    __syncthreads();

#pragma unroll 1
    for (int s = 0; s < NST; ++s) {
        const float* buf = &sm[(s & 1) ? STG1_OFF : STG0_OFF];
        float2 wn;
        const bool have = (s + 1 < NST);
        if (have)
            wn = *reinterpret_cast<const float2*>(
                     &W[(size_t)((s + 1) * KCH + srow) * ldw + coff + sc2]);
#pragma unroll
        for (int kk = 0; kk < KCH; ++kk) {
            const int k = s * KCH + kk;
            u64t a0, a1;
            lds128(a0, a1, &sm[in_off + k * SP + r0]);
            const float* B = buf + (kk * 128 + tx) * 2;
#pragma unroll
            for (int j = 0; j < 8; ++j) {
                u64t bb = *reinterpret_cast<const u64t*>(B + j * 32);
                fma2(acc[0][j], a0, bb);
                fma2(acc[1][j], a1, bb);
            }
        }
        if (have) {
            float* p = &sm[((s & 1) ? STG0_OFF : STG1_OFF) + (srow * 128 + sc2) * 2];
            *reinterpret_cast<float2*>(p)     = make_float2(wn.x, wn.x);
            *reinterpret_cast<float2*>(p + 2) = make_float2(wn.y, wn.y);
        }
        __syncthreads();
    }
    // epilogue: bias (+tanh) -> feature-major out
#pragma unroll
    for (int j = 0; j < 8; ++j) {
        const int c = coff + tx + 16 * j;
        const float bias = sm[bias_off + c];
#pragma unroll
        for (int i = 0; i < 2; ++i) {
            float lo, hi; unpack2(acc[i][j], lo, hi);
            lo += bias; hi += bias;
            if (DOTANH) { lo = tanh_f(lo); hi = tanh_f(hi); }
            *reinterpret_cast<float2*>(&sm[out_off + c * SP + r0 + 2 * i]) =
                make_float2(lo, hi);
        }
    }
}

// ---------------- E2: 128 -> 6, tanh (z -> A256 rows 0..5) ----------------
__device__ __forceinline__ void layer_E2(float* sm)
{
    const int tid = threadIdx.x;
    if (tid < 384) {
        const int r = tid & 127;
        const int g = tid >> 7;          // 0..2 -> outputs 2g, 2g+1
        float a0 = 0.f, a1 = 0.f;
#pragma unroll 8
        for (int k = 0; k < 128; ++k) {
            float a = sm[A128_OFF + k * SP + r];
            a0 = fmaf(a, sm[C_WE2 + k * 6 + 2 * g],     a0);
            a1 = fmaf(a, sm[C_WE2 + k * 6 + 2 * g + 1], a1);
        }
        sm[A256_OFF + (2 * g)     * SP + r] = tanh_f(a0 + sm[C_BE2 + 2 * g]);
        sm[A256_OFF + (2 * g + 1) * SP + r] = tanh_f(a1 + sm[C_BE2 + 2 * g + 1]);
    }
}

// ---------------- D1: 6 -> 128, tanh (weights pre-duplicated in smem) ------
__device__ __forceinline__ void layer_D1(float* sm)
{
    const int tid = threadIdx.x;
    const int tx = tid & 15, ty = tid >> 4;
    const int r0 = ty * 4;
    u64t acc[2][8];
#pragma unroll
    for (int j = 0; j < 8; ++j) { acc[0][j] = 0ull; acc[1][j] = 0ull; }
#pragma unroll
    for (int k = 0; k < 6; ++k) {
        u64t a0, a1;
        lds128(a0, a1, &sm[A256_OFF + k * SP + r0]);
        const float* B = &sm[C_WD1D + (k * 128 + tx) * 2];
#pragma unroll
        for (int j = 0; j < 8; ++j) {
            u64t bb = *reinterpret_cast<const u64t*>(B + j * 32);
            fma2(acc[0][j], a0, bb);
            fma2(acc[1][j], a1, bb);
        }
    }
#pragma unroll
    for (int j = 0; j < 8; ++j) {
        const int c = tx + 16 * j;
        const float bias = sm[C_BD1 + c];
#pragma unroll
        for (int i = 0; i < 2; ++i) {
            float lo, hi; unpack2(acc[i][j], lo, hi);
            *reinterpret_cast<float2*>(&sm[A128_OFF + c * SP + r0 + 2 * i]) =
                make_float2(tanh_f(lo + bias), tanh_f(hi + bias));
        }
    }
}

// ---------------- O: out = sigmoid(tanh(d) @ Wo + bo) ----------------------
__device__ __forceinline__ void layer_O(float* sm, const float* __restrict__ Wo,
                                        float* __restrict__ out, int nb, int Nn)
{
    const int tid = threadIdx.x;
    const int r = tid & 127;
    const int q = tid >> 7;              // k quarter 0..3
    float p = 0.f;
#pragma unroll 8
    for (int kk = 0; kk < 64; ++kk) {
        const int k = q * 64 + kk;
        p = fmaf(tanh_f(sm[A256_OFF + k * SP + r]), __ldg(&Wo[k]), p);
    }
    sm[STG0_OFF + q * 128 + r] = p;      // stage buffer as scratch
    __syncthreads();
    if (q == 0) {
        float v = sm[STG0_OFF + r] + sm[STG0_OFF + 128 + r] +
                  sm[STG0_OFF + 256 + r] + sm[STG0_OFF + 384 + r] + sm[C_BO];
        float e;  asm("ex2.approx.f32 %0, %1;" : "=f"(e)  : "f"(-1.442695041f * v));
        float sg; asm("rcp.approx.f32 %0, %1;" : "=f"(sg) : "f"(1.0f + e));
        const int node = nb + r;
        if (node < Nn) out[node] = sg;
    }
}

// ---------------- main fused kernel ----------------
__global__ void __launch_bounds__(512, 1)
gnn_fused_kernel(const float* __restrict__ edge_attr,
                 const float* __restrict__ W1,  const float* __restrict__ b1,
                 const float* __restrict__ We1, const float* __restrict__ be1,
                 const float* __restrict__ We2, const float* __restrict__ be2,
                 const float* __restrict__ Wd1, const float* __restrict__ bd1,
                 const float* __restrict__ Wd2, const float* __restrict__ bd2,
                 const float* __restrict__ Wo,  const float* __restrict__ bo,
                 float* __restrict__ out, int Nn, int ntiles)
{
    extern __shared__ float sm[];
    const int tid = threadIdx.x;

    // cache small constants once per block
    if (tid < 256) sm[C_B1  + tid] = b1[tid];
    if (tid < 128) sm[C_BE1 + tid] = be1[tid];
    for (int i = tid; i < 768; i += 512) sm[C_WE2 + i] = We2[i];
    if (tid < 6)   sm[C_BE2 + tid] = be2[tid];
    for (int i = tid; i < 768; i += 512) {          // Wd1 duplicated (w,w)
        const float w = Wd1[i];
        *reinterpret_cast<float2*>(&sm[C_WD1D + 2 * i]) = make_float2(w, w);
    }
    if (tid < 128) sm[C_BD1 + tid] = bd1[tid];
    if (tid < 256) sm[C_BD2 + tid] = bd2[tid];
    if (tid == 0)  sm[C_BO] = bo[0];

    for (int tile = blockIdx.x; tile < ntiles; tile += gridDim.x) {
        const int nb = tile * TN;
        __syncthreads();   // consts on first iter / prev-tile buffers consumed

        // load msgs tile (TN x 16) -> transposed [16][SP] in A128 region
        {
            const int node = tid >> 2;
            const int kq   = (tid & 3) * 4;
            float4 v = make_float4(0.f, 0.f, 0.f, 0.f);
            if (nb + node < Nn)
                v = *reinterpret_cast<const float4*>(
                        &edge_attr[(size_t)(nb + node) * 16 + kq]);
            sm[A128_OFF + (kq + 0) * SP + node] = v.x;
            sm[A128_OFF + (kq + 1) * SP + node] = v.y;
            sm[A128_OFF + (kq + 2) * SP + node] = v.z;
            sm[A128_OFF + (kq + 3) * SP + node] = v.w;
        }
        __syncthreads();

        gemm_stream<16,  true >(sm, A128_OFF, W1,  256, 0,   C_B1,  A256_OFF); // L1 lo
        gemm_stream<16,  true >(sm, A128_OFF, W1,  256, 128, C_B1,  A256_OFF); // L1 hi
        __syncthreads();
        gemm_stream<256, true >(sm, A256_OFF, We1, 128, 0,   C_BE1, A128_OFF); // E1
        __syncthreads();
        layer_E2(sm);                                                          // -> z
        __syncthreads();
        layer_D1(sm);                                                          // -> A128
        __syncthreads();
        gemm_stream<128, false>(sm, A128_OFF, Wd2, 256, 0,   C_BD2, A256_OFF); // D2 lo
        gemm_stream<128, false>(sm, A128_OFF, Wd2, 256, 128, C_BD2, A256_OFF); // D2 hi
        __syncthreads();
        layer_O(sm, Wo, out, nb, Nn);
    }
}

// ---------------- launch ----------------
extern "C" void kernel_launch(void* const* d_in, const int* in_sizes, int n_in,
                              void* d_out, int out_size)
{
    const float* edge_attr = (const float*)d_in[2];
    const float* W1  = (const float*)d_in[3];
    const float* b1  = (const float*)d_in[4];
    const float* We1 = (const float*)d_in[5];
    const float* be1 = (const float*)d_in[6];
    const float* We2 = (const float*)d_in[7];
    const float* be2 = (const float*)d_in[8];
    const float* Wd1 = (const float*)d_in[9];
    const float* bd1 = (const float*)d_in[10];
    const float* Wd2 = (const float*)d_in[11];
    const float* bd2 = (const float*)d_in[12];
    const float* Wo  = (const float*)d_in[13];
    const float* bo  = (const float*)d_in[14];
    float* out = (float*)d_out;

    const int Nn = out_size;
    const int ntiles = (Nn + TN - 1) / TN;

    cudaFuncSetAttribute(gnn_fused_kernel,
                         cudaFuncAttributeMaxDynamicSharedMemorySize, SMEM_BYTES);
    int sms = 148;
    cudaDeviceGetAttribute(&sms, cudaDevAttrMultiProcessorCount, 0);
    const int grid = ntiles < sms ? ntiles : sms;

    gnn_fused_kernel<<<grid, 512, SMEM_BYTES>>>(
        edge_attr, W1, b1, We1, be1, We2, be2, Wd1, bd1, Wd2, bd2, Wo, bo,
        out, Nn, ntiles);
}

// round 4
// speedup vs baseline: 1.3873x; 1.3873x over previous
#include <cuda_runtime.h>

// ---------------- configuration ----------------
#define TN   128          // nodes per tile
#define SP   130          // activation row stride (floats), even (8B-aligned pairs)
#define KCH  8            // k rows per staged chunk (ping-pong)

// ---------------- shared memory layout (float offsets) ----------------
#define A256_OFF  0
#define A128_OFF  (256*SP)                   // 33280
#define STG0_OFF  (A128_OFF + 128*SP)        // 49920 (KCH*128 dup u64 = 2048 fl)
#define STG1_OFF  (STG0_OFF + KCH*128*2)     // 51968
#define C_B1      (STG1_OFF + KCH*128*2)     // 54016
#define C_BE1     (C_B1   + 256)
#define C_WE2     (C_BE1  + 128)             // 768 (128x6)
#define C_BE2     (C_WE2  + 768)             // 8 (6 used)
#define C_WD1D    (C_BE2  + 8)               // 1536: 6x128 duplicated (w,w)
#define C_BD1     (C_WD1D + 1536)
#define C_BD2     (C_BD1  + 128)
#define C_WO      (C_BD2  + 256)             // 256
#define C_BO      (C_WO   + 256)
#define SMEM_FLOATS (C_BO + 4)
#define SMEM_BYTES  (SMEM_FLOATS * 4)        // 229,440 B <= 232,448 opt-in

typedef unsigned long long u64t;

__device__ __forceinline__ void fma2(u64t& d, u64t a, u64t b) {
    asm("fma.rn.f32x2 %0, %1, %2, %0;" : "+l"(d) : "l"(a), "l"(b));
}
__device__ __forceinline__ void unpack2(u64t v, float& lo, float& hi) {
    asm("mov.b64 {%0, %1}, %2;" : "=f"(lo), "=f"(hi) : "l"(v));
}
// tanh(x) = 1 - 2/(e^{2x}+1): clamp-free, 2 MUFU + 3 fma-pipe, rel err ~1e-6
__device__ __forceinline__ float tanh_f(float x) {
    float e; asm("ex2.approx.f32 %0, %1;" : "=f"(e) : "f"(x * 2.885390082f));
    float r; asm("rcp.approx.f32 %0, %1;" : "=f"(r) : "f"(e + 1.0f));
    return fmaf(-2.0f, r, 1.0f);
}
// stage one float4 of W, duplicated (w,w) pairs, into stage buffer
__device__ __forceinline__ void dupstore(float* sm, int off, int srow, int sc4, float4 w) {
    float* p = &sm[off + (srow * 128 + sc4) * 2];
    *reinterpret_cast<float2*>(p + 0) = make_float2(w.x, w.x);
    *reinterpret_cast<float2*>(p + 2) = make_float2(w.y, w.y);
    *reinterpret_cast<float2*>(p + 4) = make_float2(w.z, w.z);
    *reinterpret_cast<float2*>(p + 6) = make_float2(w.w, w.w);
}

// ---------------- streamed GEMM over 128 output cols ----------------
// out[c][r] = (tanh?)( sum_k in[k][r] * W[k*ldw + coff + c] + bias[coff+c] )
// 256 threads: tx=tid&15 (cols tx+16j), ty=tid>>4 (rows r0=8ty, 4 f32x2 pairs).
// W staged PRE-DUPLICATED as (w,w) u64 -> B is one LDS.64, no pack.
// A loads are warp-broadcast (2 distinct ty/warp). Ping-pong, 1 barrier/stage.
template<int K, bool DOTANH>
__device__ __forceinline__ void gemm_stream(float* sm, int in_off,
        const float* __restrict__ W, int ldw, int coff, int bias_off, int out_off)
{
    const int tid = threadIdx.x;
    const int tx = tid & 15, ty = tid >> 4;
    const int r0 = ty * 8;
    const int srow = tid >> 5;           // 0..7 staging row within chunk
    const int sc4  = (tid & 31) * 4;     // 0,4,...,124 staging col quad

    u64t acc[4][8];
#pragma unroll
    for (int i = 0; i < 4; ++i)
#pragma unroll
        for (int j = 0; j < 8; ++j) acc[i][j] = 0ull;

    // prologue: stage chunk 0
    dupstore(sm, STG0_OFF, srow, sc4,
             *reinterpret_cast<const float4*>(&W[(size_t)srow * ldw + coff + sc4]));
    __syncthreads();

    const int NST = K / KCH;
#pragma unroll 1
    for (int s = 0; s < NST; ++s) {
        const float* buf = &sm[(s & 1) ? STG1_OFF : STG0_OFF];
        float4 wn;
        const bool have = (s + 1 < NST);
        if (have)
            wn = *reinterpret_cast<const float4*>(
                     &W[(size_t)((s + 1) * KCH + srow) * ldw + coff + sc4]);
#pragma unroll
        for (int kk = 0; kk < KCH; ++kk) {
            const float* A = &sm[in_off + (s * KCH + kk) * SP + r0];
            u64t a0 = *reinterpret_cast<const u64t*>(A + 0);
            u64t a1 = *reinterpret_cast<const u64t*>(A + 2);
            u64t a2 = *reinterpret_cast<const u64t*>(A + 4);
            u64t a3 = *reinterpret_cast<const u64t*>(A + 6);
            const float* B = buf + (kk * 128 + tx) * 2;
#pragma unroll
            for (int j = 0; j < 8; ++j) {
                u64t bb = *reinterpret_cast<const u64t*>(B + j * 32);
                fma2(acc[0][j], a0, bb);
                fma2(acc[1][j], a1, bb);
                fma2(acc[2][j], a2, bb);
                fma2(acc[3][j], a3, bb);
            }
        }
        if (have) dupstore(sm, (s & 1) ? STG0_OFF : STG1_OFF, srow, sc4, wn);
        __syncthreads();
    }
    // epilogue: bias (+tanh) -> feature-major out
#pragma unroll
    for (int j = 0; j < 8; ++j) {
        const int c = coff + tx + 16 * j;
        const float bias = sm[bias_off + c];
#pragma unroll
        for (int i = 0; i < 4; ++i) {
            float lo, hi; unpack2(acc[i][j], lo, hi);
            lo += bias; hi += bias;
            if (DOTANH) { lo = tanh_f(lo); hi = tanh_f(hi); }
            *reinterpret_cast<float2*>(&sm[out_off + c * SP + r0 + 2 * i]) =
                make_float2(lo, hi);
        }
    }
}

// ---------------- E2: 128 -> 6, tanh (z -> A256 rows 0..5) ----------------
__device__ __forceinline__ void layer_E2(float* sm)
{
    const int tid = threadIdx.x;
    const int r = tid & 127;
    const int g = tid >> 7;              // 0/1 -> outputs 3g..3g+2
    float a0 = 0.f, a1 = 0.f, a2 = 0.f;
#pragma unroll 8
    for (int k = 0; k < 128; ++k) {
        const float a = sm[A128_OFF + k * SP + r];
        const float* w = &sm[C_WE2 + k * 6 + g * 3];
        a0 = fmaf(a, w[0], a0);
        a1 = fmaf(a, w[1], a1);
        a2 = fmaf(a, w[2], a2);
    }
    const float* be = &sm[C_BE2 + g * 3];
    sm[A256_OFF + (g * 3 + 0) * SP + r] = tanh_f(a0 + be[0]);
    sm[A256_OFF + (g * 3 + 1) * SP + r] = tanh_f(a1 + be[1]);
    sm[A256_OFF + (g * 3 + 2) * SP + r] = tanh_f(a2 + be[2]);
}

// ---------------- D1: 6 -> 128, tanh (weights pre-duplicated) ----------------
__device__ __forceinline__ void layer_D1(float* sm)
{
    const int tid = threadIdx.x;
    const int tx = tid & 15, ty = tid >> 4;
    const int r0 = ty * 8;
    u64t acc[4][8];
#pragma unroll
    for (int i = 0; i < 4; ++i)
#pragma unroll
        for (int j = 0; j < 8; ++j) acc[i][j] = 0ull;
#pragma unroll
    for (int k = 0; k < 6; ++k) {
        const float* A = &sm[A256_OFF + k * SP + r0];
        u64t a0 = *reinterpret_cast<const u64t*>(A + 0);
        u64t a1 = *reinterpret_cast<const u64t*>(A + 2);
        u64t a2 = *reinterpret_cast<const u64t*>(A + 4);
        u64t a3 = *reinterpret_cast<const u64t*>(A + 6);
        const float* B = &sm[C_WD1D + (k * 128 + tx) * 2];
#pragma unroll
        for (int j = 0; j < 8; ++j) {
            u64t bb = *reinterpret_cast<const u64t*>(B + j * 32);
            fma2(acc[0][j], a0, bb);
            fma2(acc[1][j], a1, bb);
            fma2(acc[2][j], a2, bb);
            fma2(acc[3][j], a3, bb);
        }
    }
#pragma unroll
    for (int j = 0; j < 8; ++j) {
        const int c = tx + 16 * j;
        const float bias = sm[C_BD1 + c];
#pragma unroll
        for (int i = 0; i < 4; ++i) {
            float lo, hi; unpack2(acc[i][j], lo, hi);
            *reinterpret_cast<float2*>(&sm[A128_OFF + c * SP + r0 + 2 * i]) =
                make_float2(tanh_f(lo + bias), tanh_f(hi + bias));
        }
    }
}

// ---------------- O: out = sigmoid(tanh(d) @ Wo + bo) ----------------------
__device__ __forceinline__ void layer_O(float* sm, float* __restrict__ out,
                                        int nb, int Nn)
{
    const int tid = threadIdx.x;
    const int r = tid & 127;
    const int q = tid >> 7;              // k half 0/1
    float p = 0.f;
#pragma unroll 8
    for (int kk = 0; kk < 128; ++kk) {
        const int k = q * 128 + kk;
        p = fmaf(tanh_f(sm[A256_OFF + k * SP + r]), sm[C_WO + k], p);
    }
    sm[STG0_OFF + q * 128 + r] = p;      // stage buffer as scratch
    __syncthreads();
    if (q == 0) {
        const float v = sm[STG0_OFF + r] + sm[STG0_OFF + 128 + r] + sm[C_BO];
        float e;  asm("ex2.approx.f32 %0, %1;" : "=f"(e)  : "f"(-1.442695041f * v));
        float sg; asm("rcp.approx.f32 %0, %1;" : "=f"(sg) : "f"(1.0f + e));
        const int node = nb + r;
        if (node < Nn) out[node] = sg;
    }
}

// ---------------- main fused kernel ----------------
__global__ void __launch_bounds__(256, 1)
gnn_fused_kernel(const float* __restrict__ edge_attr,
                 const float* __restrict__ W1,  const float* __restrict__ b1,
                 const float* __restrict__ We1, const float* __restrict__ be1,
                 const float* __restrict__ We2, const float* __restrict__ be2,
                 const float* __restrict__ Wd1, const float* __restrict__ bd1,
                 const float* __restrict__ Wd2, const float* __restrict__ bd2,
                 const float* __restrict__ Wo,  const float* __restrict__ bo,
                 float* __restrict__ out, int Nn, int ntiles)
{
    extern __shared__ float sm[];
    const int tid = threadIdx.x;

    // cache constants once per block
    if (tid < 256) sm[C_B1  + tid] = b1[tid];
    if (tid < 128) sm[C_BE1 + tid] = be1[tid];
    for (int i = tid; i < 768; i += 256) sm[C_WE2 + i] = We2[i];
    if (tid < 6)   sm[C_BE2 + tid] = be2[tid];
    for (int i = tid; i < 768; i += 256) {          // Wd1 duplicated (w,w)
        const float w = Wd1[i];
        *reinterpret_cast<float2*>(&sm[C_WD1D + 2 * i]) = make_float2(w, w);
    }
    if (tid < 128) sm[C_BD1 + tid] = bd1[tid];
    if (tid < 256) sm[C_BD2 + tid] = bd2[tid];
    if (tid < 256) sm[C_WO  + tid] = Wo[tid];
    if (tid == 0)  sm[C_BO] = bo[0];

    for (int tile = blockIdx.x; tile < ntiles; tile += gridDim.x) {
        const int nb = tile * TN;
        __syncthreads();   // consts ready / prev-tile buffers consumed

        // load msgs tile (TN x 16) -> transposed [16][SP] in A128 region
#pragma unroll
        for (int q = 0; q < 2; ++q) {
            const int idx4 = tid + q * 256;       // 512 float4 = 2048 floats
            const int node = idx4 >> 2;
            const int kq   = (idx4 & 3) * 4;
            float4 v = make_float4(0.f, 0.f, 0.f, 0.f);
            if (nb + node < Nn)
                v = *reinterpret_cast<const float4*>(
                        &edge_attr[(size_t)(nb + node) * 16 + kq]);
            sm[A128_OFF + (kq + 0) * SP + node] = v.x;
            sm[A128_OFF + (kq + 1) * SP + node] = v.y;
            sm[A128_OFF + (kq + 2) * SP + node] = v.z;
            sm[A128_OFF + (kq + 3) * SP + node] = v.w;
        }
        __syncthreads();

        gemm_stream<16,  true >(sm, A128_OFF, W1,  256, 0,   C_B1,  A256_OFF); // L1 lo
        gemm_stream<16,  true >(sm, A128_OFF, W1,  256, 128, C_B1,  A256_OFF); // L1 hi
        __syncthreads();
        gemm_stream<256, true >(sm, A256_OFF, We1, 128, 0,   C_BE1, A128_OFF); // E1
        __syncthreads();
        layer_E2(sm);                                                          // -> z
        __syncthreads();
        layer_D1(sm);                                                          // -> A128
        __syncthreads();
        gemm_stream<128, false>(sm, A128_OFF, Wd2, 256, 0,   C_BD2, A256_OFF); // D2 lo
        gemm_stream<128, false>(sm, A128_OFF, Wd2, 256, 128, C_BD2, A256_OFF); // D2 hi
        __syncthreads();
        layer_O(sm, out, nb, Nn);
    }
}

// ---------------- launch ----------------
extern "C" void kernel_launch(void* const* d_in, const int* in_sizes, int n_in,
                              void* d_out, int out_size)
{
    const float* edge_attr = (const float*)d_in[2];
    const float* W1  = (const float*)d_in[3];
    const float* b1  = (const float*)d_in[4];
    const float* We1 = (const float*)d_in[5];
    const float* be1 = (const float*)d_in[6];
    const float* We2 = (const float*)d_in[7];
    const float* be2 = (const float*)d_in[8];
    const float* Wd1 = (const float*)d_in[9];
    const float* bd1 = (const float*)d_in[10];
    const float* Wd2 = (const float*)d_in[11];
    const float* bd2 = (const float*)d_in[12];
    const float* Wo  = (const float*)d_in[13];
    const float* bo  = (const float*)d_in[14];
    float* out = (float*)d_out;

    const int Nn = out_size;
    const int ntiles = (Nn + TN - 1) / TN;

    cudaFuncSetAttribute(gnn_fused_kernel,
                         cudaFuncAttributeMaxDynamicSharedMemorySize, SMEM_BYTES);
    int sms = 148;
    cudaDeviceGetAttribute(&sms, cudaDevAttrMultiProcessorCount, 0);
    const int grid = ntiles < sms ? ntiles : sms;

    gnn_fused_kernel<<<grid, 256, SMEM_BYTES>>>(
        edge_attr, W1, b1, We1, be1, We2, be2, Wd1, bd1, Wd2, bd2, Wo, bo,
        out, Nn, ntiles);
}